// round 7
// baseline (speedup 1.0000x reference)
#include <cuda_runtime.h>
#include <math.h>
#include <stdint.h>
#include <cstdint>

#define NBULK        62
#define NSITES       64
#define DDIM         64
#define NBATCH       8192
#define LOGZ_BLOCKS  16
#define PSI_BLOCKS   256
#define TOTAL_BLOCKS (LOGZ_BLOCKS + PSI_BLOCKS)
#define NTHREADS     256
#define MBLK         32                     // samples per psi block

// ---------------- psi-block shared memory layout (float offsets) -------------
// env stored k-major: env[k][m], m=0..31, stride 36
#define ENV_STRIDE 36
#define SM_ENV     0                        // 64*36 = 2304 floats
#define SM_A       2304                     // 2 x 8192 floats (double-buffered site tensor)
#define SM_CFG     (SM_A + 16384)           // 2048 bytes = 512 floats (cfgS[site][m])
#define SM_RED     (SM_CFG + 512)           // 256 floats
#define SM_TOTALF  (SM_RED + 256)           // 19456 floats = 77824 bytes (2 blocks/SM fit)

// ---------------- logz-block shared memory layout (fits inside psi size) -----
#define LZ_ENV  0                           // 64*65 = 4160
#define LZ_A    4160                        // 8192
#define LZ_TMP  (LZ_A + 8192)               // 64*9 = 576
#define LZ_RED  (LZ_TMP + 576)              // 256 (also holds max word)

// ---------------- global scratch (zero-initialized at load) ------------------
__device__ float    g_envbuf[2][DDIM * DDIM];
__device__ float    g_maxarr[2][LOGZ_BLOCKS];
__device__ float    g_blocksums[PSI_BLOCKS];
__device__ float    g_logz;
__device__ unsigned g_bar_count;
__device__ volatile unsigned g_bar_gen;
__device__ unsigned g_done;                 // logz-block exit counter (resets bar gen)
__device__ unsigned g_fin;                  // finisher counter (257 arrivals)

typedef unsigned long long ull;

__device__ __forceinline__ void cp16(unsigned dst, const void* src) {
    asm volatile("cp.async.cg.shared.global [%0], [%1], 16;" :: "r"(dst), "l"(src) : "memory");
}
__device__ __forceinline__ void cp_commit() {
    asm volatile("cp.async.commit_group;" ::: "memory");
}
__device__ __forceinline__ void cp_wait0() {
    asm volatile("cp.async.wait_group 0;" ::: "memory");
}
// packed fp32x2 FMA (FFMA2 — 2 FMAs per issue)
__device__ __forceinline__ ull ffma2(ull a, ull b, ull c) {
    ull d;
    asm("fma.rn.f32x2 %0, %1, %2, %3;" : "=l"(d) : "l"(a), "l"(b), "l"(c));
    return d;
}
__device__ __forceinline__ ull packdup(float x) {
    ull r;
    unsigned xi = __float_as_uint(x);
    asm("mov.b64 %0, {%1, %2};" : "=l"(r) : "r"(xi), "r"(xi));
    return r;
}

// Barrier arrival/spin (thread 0 only). Caller brackets with __syncthreads.
__device__ __forceinline__ void gbar_arrive_spin(unsigned target) {
    __threadfence();
    unsigned t = atomicAdd(&g_bar_count, 1u);
    if (t == LOGZ_BLOCKS - 1) {
        g_bar_count = 0;
        __threadfence();
        g_bar_gen = target;
    } else {
        while (g_bar_gen < target) { }
    }
}

__global__ __launch_bounds__(NTHREADS, 2)
void main_kernel(const int* __restrict__ cfg,
                 const float* __restrict__ left,
                 const float* __restrict__ bulk,
                 const float* __restrict__ right,
                 float* __restrict__ out) {
    extern __shared__ float smem[];
    const int tid = threadIdx.x;

    if (blockIdx.x < LOGZ_BLOCKS) {
        // ==================== log-Z path: 16 cooperating blocks ====================
        unsigned genl = 0;
        const int jb = blockIdx.x << 2;
        unsigned* maxw = (unsigned*)(smem + LZ_RED);

        if (blockIdx.x == 0) {
            for (int idx = tid; idx < DDIM * DDIM; idx += NTHREADS) {
                int i = idx >> 6, j = idx & 63;
                g_envbuf[0][idx] = left[i] * left[j] + left[64 + i] * left[64 + j];
            }
        }
        __syncthreads();
        if (tid == 0) gbar_arrive_spin(++genl);
        __syncthreads();
        __threadfence();

        float inv_scale = 1.0f, log_scale = 0.0f;

        for (int t = 0; t < NBULK; t++) {
            const int cur = t & 1, nxt = cur ^ 1;
            if (tid == 0) *maxw = 0u;
            // stage A (both phys slices), coalesced
            const float4* asrc = (const float4*)(bulk + (size_t)t * 8192);
            float4* adst = (float4*)(smem + LZ_A);
#pragma unroll
            for (int i = 0; i < 8; i++) adst[tid + (i << 8)] = asrc[tid + (i << 8)];
            // stage env with lazy rescale from previous step
            for (int idx = tid; idx < DDIM * DDIM; idx += NTHREADS) {
                int d = idx >> 6, e = idx & 63;
                smem[LZ_ENV + d * 65 + e] = __ldcg(&g_envbuf[cur][idx]) * inv_scale;
            }
            __syncthreads();

            const int d  = tid & 63;
            const int jj = tid >> 6;
            // phase 1: tmp_p[d][jj] = sum_e env[d][e] * A_p[e][jb+jj]
            float t0 = 0.0f, t1 = 0.0f;
#pragma unroll 8
            for (int e = 0; e < 64; e++) {
                float ev = smem[LZ_ENV + d * 65 + e];
                t0 = fmaf(ev, smem[LZ_A + e * 128 + jb + jj], t0);
                t1 = fmaf(ev, smem[LZ_A + e * 128 + 64 + jb + jj], t1);
            }
            smem[LZ_TMP + d * 9 + jj]     = t0;
            smem[LZ_TMP + d * 9 + 4 + jj] = t1;
            __syncthreads();

            // phase 2: out[i][jb+jj] = sum_p sum_dd A_p[dd][i] * tmp_p[dd][jj]  (i == d)
            float o = 0.0f;
#pragma unroll 8
            for (int dd = 0; dd < 64; dd++) {
                o = fmaf(smem[LZ_A + dd * 128 + d],      smem[LZ_TMP + dd * 9 + jj],     o);
                o = fmaf(smem[LZ_A + dd * 128 + 64 + d], smem[LZ_TMP + dd * 9 + 4 + jj], o);
            }
            g_envbuf[nxt][d * 64 + jb + jj] = o;

            // block max via shuffle + one shared atomicMax (floats >= 0 -> uint order exact)
            float am = fabsf(o);
#pragma unroll
            for (int off = 16; off > 0; off >>= 1)
                am = fmaxf(am, __shfl_xor_sync(0xffffffffu, am, off));
            if ((tid & 31) == 0) atomicMax(maxw, __float_as_uint(am));
            __syncthreads();

            if (tid == 0) {
                g_maxarr[nxt][blockIdx.x] = __uint_as_float(*maxw);
                gbar_arrive_spin(++genl);
            }
            __syncthreads();
            __threadfence();

            float mx = 0.0f;
#pragma unroll
            for (int b = 0; b < LOGZ_BLOCKS; b++) mx = fmaxf(mx, __ldcg(&g_maxarr[nxt][b]));
            float scale = fmaxf(mx, 1e-30f);
            log_scale += logf(scale);
            inv_scale = 1.0f / scale;
        }

        // final env in g_envbuf[0] (NBULK even). z = sum(right * (env_scaled @ right))
        if (blockIdx.x == 0) {
            float part = 0.0f;
            if (tid < 128) {
                int k = tid & 63, p = tid >> 6;
                float s = 0.0f;
#pragma unroll 8
                for (int e = 0; e < 64; e++)
                    s = fmaf(__ldcg(&g_envbuf[0][k * 64 + e]), right[e * 2 + p], s);
                part = right[k * 2 + p] * s;
            }
            smem[LZ_RED + tid] = part;
            __syncthreads();
            for (int s = 128; s > 0; s >>= 1) {
                if (tid < s) smem[LZ_RED + tid] += smem[LZ_RED + tid + s];
                __syncthreads();
            }
            if (tid == 0) {
                g_logz = logf(fmaxf(smem[LZ_RED] * inv_scale, 1e-30f)) + log_scale;
                __threadfence();
                unsigned o = atomicAdd(&g_fin, 1u);
                if (o == PSI_BLOCKS) {
                    float s = 0.0f;
                    for (int i = 0; i < PSI_BLOCKS; i++) s += __ldcg(&g_blocksums[i]);
                    out[0] = g_logz - s * (1.0f / (float)NBATCH);
                    __threadfence();
                    g_fin = 0;
                    __threadfence();
                }
            }
        }

        // reset barrier generation for next graph replay (last logz block out)
        __syncthreads();
        if (tid == 0) {
            unsigned dn = atomicAdd(&g_done, 1u);
            if (dn == LOGZ_BLOCKS - 1) {
                g_done = 0;
                g_bar_gen = 0;
                __threadfence();
            }
        }
        return;
    }

    // ==================== psi path: 256 blocks x 32 samples, 2 blocks/SM ======
    // Thread tile: 4 m (mg=tid&7) x [2p x 2 j] (jg=tid>>3). Compute BOTH phys
    // branches (FFMA2, no selects), select once per site at writeback.
    const int bi = blockIdx.x - LOGZ_BLOCKS;
    const int m0 = bi * MBLK;
    unsigned char* cfgS = (unsigned char*)(smem + SM_CFG);
    const unsigned smemA_base = (unsigned)__cvta_generic_to_shared(smem + SM_A);

    const int mg = tid & 7;    // m group: m = 4*mg .. 4*mg+3  (m in 0..31)
    const int jg = tid >> 3;   // j group: j = 2*jg, 2*jg+1    (jg in 0..31)

    // kick off cp.async for site-0 A tile into buffer 0 (2048 float4 / 256 thr)
    {
        const float4* src = (const float4*)bulk;
#pragma unroll
        for (int i = 0; i < 8; i++)
            cp16(smemA_base + (unsigned)(tid + (i << 8)) * 16u, src + tid + (i << 8));
        cp_commit();
    }

    // stage configurations: cfgS[site][m]  (64 sites x 32 m)
    for (int idx = tid; idx < 64 * MBLK; idx += NTHREADS) {
        int mm = idx >> 6, s = idx & 63;
        cfgS[s * MBLK + mm] = (unsigned char)cfg[(size_t)(m0 + mm) * 64 + s];
    }
    __syncthreads();

    // init env[k][m] = left[cfg0(m)][k]
    for (int idx = tid; idx < 64 * MBLK; idx += NTHREADS) {
        int k = idx >> 5, mm = idx & 31;
        smem[SM_ENV + k * ENV_STRIDE + mm] = left[(int)cfgS[mm] * 64 + k];
    }

    for (int t = 0; t < NBULK; t++) {
        cp_wait0();
        __syncthreads();       // A[t] resident; env writes from t-1 published

        if (t + 1 < NBULK) {
            const float4* src = (const float4*)(bulk + (size_t)(t + 1) * 8192);
            unsigned dst = smemA_base + (unsigned)(((t + 1) & 1) * 32768u);
#pragma unroll
            for (int i = 0; i < 8; i++)
                cp16(dst + (unsigned)(tid + (i << 8)) * 16u, src + tid + (i << 8));
            cp_commit();
        }

        const float* A0 = smem + SM_A + (t & 1) * 8192 + 2 * jg;        // p=0
        const float* E  = smem + SM_ENV + 4 * mg;

        // acc[mm][p] : f32x2 over the j pair
        ull acc[4][2];
#pragma unroll
        for (int a = 0; a < 4; a++) { acc[a][0] = 0ull; acc[a][1] = 0ull; }

#pragma unroll 8
        for (int k = 0; k < 64; k++) {
            const float4 e = *(const float4*)(E + k * ENV_STRIDE);
            const ull b0 = *(const ull*)(A0 + k * 128);
            const ull b1 = *(const ull*)(A0 + k * 128 + 64);
            const ull e0 = packdup(e.x), e1 = packdup(e.y),
                      e2 = packdup(e.z), e3 = packdup(e.w);
            acc[0][0] = ffma2(e0, b0, acc[0][0]);
            acc[0][1] = ffma2(e0, b1, acc[0][1]);
            acc[1][0] = ffma2(e1, b0, acc[1][0]);
            acc[1][1] = ffma2(e1, b1, acc[1][1]);
            acc[2][0] = ffma2(e2, b0, acc[2][0]);
            acc[2][1] = ffma2(e2, b1, acc[2][1]);
            acc[3][0] = ffma2(e3, b0, acc[3][0]);
            acc[3][1] = ffma2(e3, b1, acc[3][1]);
        }
        __syncthreads();   // all env reads done -> safe to overwrite env in place

        // select branch per m and write env_new[j][m] (k-major for next site)
        const unsigned s4 = *(const unsigned*)(cfgS + (t + 1) * MBLK + 4 * mg);
#pragma unroll
        for (int mm = 0; mm < 4; mm++) {
            const bool s = ((s4 >> (8 * mm)) & 0xffu) != 0u;
            const ull r = s ? acc[mm][1] : acc[mm][0];
            const float flo = __uint_as_float((unsigned)(r & 0xffffffffull));
            const float fhi = __uint_as_float((unsigned)(r >> 32));
            float* w = smem + SM_ENV + 4 * mg + mm;
            w[(2 * jg + 0) * ENV_STRIDE] = flo;
            w[(2 * jg + 1) * ENV_STRIDE] = fhi;
        }
        // loop-top __syncthreads publishes env_new before the next k loop
    }
    __syncthreads();

    // psi[m] = sum_k env[k][m] * right[k][cfg_last(m)]
    {
        const int m = tid & 31, part = tid >> 5;   // 8 parts x 8 k
        const int sl = cfgS[63 * MBLK + m];
        float p = 0.0f;
#pragma unroll
        for (int kk = 0; kk < 8; kk++) {
            int k = part * 8 + kk;
            p = fmaf(smem[SM_ENV + k * ENV_STRIDE + m], right[k * 2 + sl], p);
        }
        smem[SM_RED + part * 32 + m] = p;
        __syncthreads();
        if (tid < 32) {
            float psi = 0.0f;
#pragma unroll
            for (int pp = 0; pp < 8; pp++) psi += smem[SM_RED + pp * 32 + tid];
            smem[SM_RED + tid] = logf(fmaxf(psi * psi, 1e-12f));
        }
        __syncthreads();
        if (tid == 0) {
            float s = 0.0f;
#pragma unroll 8
            for (int i = 0; i < 32; i++) s += smem[SM_RED + i];
            g_blocksums[bi] = s;
            __threadfence();
            unsigned o = atomicAdd(&g_fin, 1u);
            if (o == PSI_BLOCKS) {   // last arrival overall (incl. logz) -> finish
                float tot = 0.0f;
                for (int i = 0; i < PSI_BLOCKS; i++) tot += __ldcg(&g_blocksums[i]);
                out[0] = g_logz - tot * (1.0f / (float)NBATCH);
                __threadfence();
                g_fin = 0;
                __threadfence();
            }
        }
    }
}

extern "C" void kernel_launch(void* const* d_in, const int* in_sizes, int n_in,
                              void* d_out, int out_size) {
    const int*   cfg   = (const int*)d_in[0];
    const float* left  = (const float*)d_in[1];
    const float* bulk  = (const float*)d_in[2];
    const float* right = (const float*)d_in[3];

    cudaFuncSetAttribute(main_kernel, cudaFuncAttributeMaxDynamicSharedMemorySize,
                         SM_TOTALF * 4);

    main_kernel<<<TOTAL_BLOCKS, NTHREADS, SM_TOTALF * 4>>>(cfg, left, bulk, right,
                                                           (float*)d_out);
}

// round 9
// speedup vs baseline: 1.2416x; 1.2416x over previous
#include <cuda_runtime.h>
#include <math.h>
#include <stdint.h>
#include <cstdint>

#define NBULK        62
#define DDIM         64
#define NBATCH       8192
#define LOGZ_BLOCKS  16
#define PSI_BLOCKS   128
#define TOTAL_BLOCKS (LOGZ_BLOCKS + PSI_BLOCKS)
#define NTHREADS     256
#define MBLK         64

// ---------------- psi-block shared memory layout (float offsets) -------------
#define ENV_STRIDE 68
#define SM_ENV     0                        // 64*68 = 4352 (env[m][k], row-major)
#define SM_RIGHT   4352                     // 128 floats
#define SM_RED     4480                     // 128 floats ([2][64])
#define SM_CFG     4608                     // 1024 floats = 4096 B (cfgS[site][m])
#define SM_B       5632                     // byte 22528 (128B aligned); 2 x 16384 floats
#define SM_TOTALF  (5632 + 2 * 16384)       // 38400 floats = 153600 bytes

// ---------------- logz-block shared memory layout (fits inside psi size) -----
#define LZ_ENV  0
#define LZ_A    4160
#define LZ_TMP  (LZ_A + 8192)
#define LZ_RED  (LZ_TMP + 576)

// ---------------- global scratch (zero-initialized at load) ------------------
__device__ float    g_bulkT[(size_t)NBULK * 16384];   // per site: Bhi frag-order[8192] | Blo[8192]
__device__ float    g_envbuf[2][DDIM * DDIM];
__device__ float    g_maxarr[2][LOGZ_BLOCKS];
__device__ float    g_blocksums[PSI_BLOCKS];
__device__ float    g_logz;
__device__ unsigned g_bar_count;
__device__ volatile unsigned g_bar_gen;
__device__ unsigned g_done;
__device__ unsigned g_fin;

__device__ __forceinline__ void cp16(unsigned dst, const void* src) {
    asm volatile("cp.async.cg.shared.global [%0], [%1], 16;" :: "r"(dst), "l"(src) : "memory");
}
__device__ __forceinline__ void cp_commit() { asm volatile("cp.async.commit_group;" ::: "memory"); }
__device__ __forceinline__ void cp_wait0()  { asm volatile("cp.async.wait_group 0;" ::: "memory"); }

// m16n8k8 tf32 MMA, f32 accumulate in-place
__device__ __forceinline__ void mma8(float& d0, float& d1, float& d2, float& d3,
                                     unsigned a0, unsigned a1, unsigned a2, unsigned a3,
                                     unsigned b0, unsigned b1) {
    asm volatile("mma.sync.aligned.m16n8k8.row.col.f32.tf32.tf32.f32 "
                 "{%0,%1,%2,%3}, {%4,%5,%6,%7}, {%8,%9}, {%0,%1,%2,%3};"
                 : "+f"(d0), "+f"(d1), "+f"(d2), "+f"(d3)
                 : "r"(a0), "r"(a1), "r"(a2), "r"(a3), "r"(b0), "r"(b1));
}

__device__ __forceinline__ void gbar_arrive_spin(unsigned target) {
    __threadfence();
    unsigned t = atomicAdd(&g_bar_count, 1u);
    if (t == LOGZ_BLOCKS - 1) {
        g_bar_count = 0;
        __threadfence();
        g_bar_gen = target;
    } else {
        while (g_bar_gen < target) { }
    }
}

// ============ pre-pass: bulk -> tf32 hi/lo in B-fragment order ===============
// Fragment order (m16n8k8.row.col): per (kt, ntp, lane): float4
// {b0(nt=2ntp), b1(2ntp), b0(2ntp+1), b1(2ntp+1)}, where for lane:
// b0 = B[kt*8 + lane%4][nt*8 + lane/4], b1 = B[kt*8 + lane%4 + 4][nt*8 + lane/4].
__global__ void pre_kernel(const float* __restrict__ bulk) {
    const int t = blockIdx.x;
    const float* src = bulk + (size_t)t * 8192;   // [k][n], n = p*64+j
    float* dst = g_bulkT + (size_t)t * 16384;
    for (int idx = threadIdx.x; idx < 8192; idx += blockDim.x) {
        int k = idx >> 7, n = idx & 127;
        float v = src[idx];
        unsigned hb = __float_as_uint(v) & 0xFFFFE000u;
        float hif = __uint_as_float(hb);
        float lof = v - hif;
        unsigned lb = __float_as_uint(lof) & 0xFFFFE000u;
        int kt   = k >> 3;
        int lane = ((n & 7) << 2) | (k & 3);
        int b    = (k >> 2) & 1;
        int ntp  = n >> 4;
        int q    = (((n >> 3) & 1) << 1) | b;
        int off  = kt * 1024 + ntp * 128 + lane * 4 + q;
        dst[off]        = __uint_as_float(hb);
        dst[8192 + off] = __uint_as_float(lb);
    }
}

__global__ __launch_bounds__(NTHREADS)
void main_kernel(const int* __restrict__ cfg,
                 const float* __restrict__ left,
                 const float* __restrict__ bulk,
                 const float* __restrict__ right,
                 float* __restrict__ out) {
    extern __shared__ float smem[];
    const int tid = threadIdx.x;

    if (blockIdx.x < LOGZ_BLOCKS) {
        // ==================== log-Z path: 16 cooperating blocks (unchanged) =====
        unsigned genl = 0;
        const int jb = blockIdx.x << 2;
        unsigned* maxw = (unsigned*)(smem + LZ_RED);

        if (blockIdx.x == 0) {
            for (int idx = tid; idx < DDIM * DDIM; idx += NTHREADS) {
                int i = idx >> 6, j = idx & 63;
                g_envbuf[0][idx] = left[i] * left[j] + left[64 + i] * left[64 + j];
            }
        }
        __syncthreads();
        if (tid == 0) gbar_arrive_spin(++genl);
        __syncthreads();
        __threadfence();

        float inv_scale = 1.0f, log_scale = 0.0f;

        for (int t = 0; t < NBULK; t++) {
            const int cur = t & 1, nxt = cur ^ 1;
            if (tid == 0) *maxw = 0u;
            const float4* asrc = (const float4*)(bulk + (size_t)t * 8192);
            float4* adst = (float4*)(smem + LZ_A);
#pragma unroll
            for (int i = 0; i < 8; i++) adst[tid + (i << 8)] = asrc[tid + (i << 8)];
            for (int idx = tid; idx < DDIM * DDIM; idx += NTHREADS) {
                int d = idx >> 6, e = idx & 63;
                smem[LZ_ENV + d * 65 + e] = __ldcg(&g_envbuf[cur][idx]) * inv_scale;
            }
            __syncthreads();

            const int d  = tid & 63;
            const int jj = tid >> 6;
            float t0 = 0.0f, t1 = 0.0f;
#pragma unroll 8
            for (int e = 0; e < 64; e++) {
                float ev = smem[LZ_ENV + d * 65 + e];
                t0 = fmaf(ev, smem[LZ_A + e * 128 + jb + jj], t0);
                t1 = fmaf(ev, smem[LZ_A + e * 128 + 64 + jb + jj], t1);
            }
            smem[LZ_TMP + d * 9 + jj]     = t0;
            smem[LZ_TMP + d * 9 + 4 + jj] = t1;
            __syncthreads();

            float o = 0.0f;
#pragma unroll 8
            for (int dd = 0; dd < 64; dd++) {
                o = fmaf(smem[LZ_A + dd * 128 + d],      smem[LZ_TMP + dd * 9 + jj],     o);
                o = fmaf(smem[LZ_A + dd * 128 + 64 + d], smem[LZ_TMP + dd * 9 + 4 + jj], o);
            }
            g_envbuf[nxt][d * 64 + jb + jj] = o;

            float am = fabsf(o);
#pragma unroll
            for (int off = 16; off > 0; off >>= 1)
                am = fmaxf(am, __shfl_xor_sync(0xffffffffu, am, off));
            if ((tid & 31) == 0) atomicMax(maxw, __float_as_uint(am));
            __syncthreads();

            if (tid == 0) {
                g_maxarr[nxt][blockIdx.x] = __uint_as_float(*maxw);
                gbar_arrive_spin(++genl);
            }
            __syncthreads();
            __threadfence();

            float mx = 0.0f;
#pragma unroll
            for (int b = 0; b < LOGZ_BLOCKS; b++) mx = fmaxf(mx, __ldcg(&g_maxarr[nxt][b]));
            float scale = fmaxf(mx, 1e-30f);
            log_scale += logf(scale);
            inv_scale = 1.0f / scale;
        }

        if (blockIdx.x == 0) {
            float part = 0.0f;
            if (tid < 128) {
                int k = tid & 63, p = tid >> 6;
                float s = 0.0f;
#pragma unroll 8
                for (int e = 0; e < 64; e++)
                    s = fmaf(__ldcg(&g_envbuf[0][k * 64 + e]), right[e * 2 + p], s);
                part = right[k * 2 + p] * s;
            }
            smem[LZ_RED + tid] = part;
            __syncthreads();
            for (int s = 128; s > 0; s >>= 1) {
                if (tid < s) smem[LZ_RED + tid] += smem[LZ_RED + tid + s];
                __syncthreads();
            }
            if (tid == 0) {
                g_logz = logf(fmaxf(smem[LZ_RED] * inv_scale, 1e-30f)) + log_scale;
                __threadfence();
                unsigned o = atomicAdd(&g_fin, 1u);
                if (o == PSI_BLOCKS) {
                    float s = 0.0f;
                    for (int i = 0; i < PSI_BLOCKS; i++) s += __ldcg(&g_blocksums[i]);
                    out[0] = g_logz - s * (1.0f / (float)NBATCH);
                    __threadfence();
                    g_fin = 0;
                    __threadfence();
                }
            }
        }

        __syncthreads();
        if (tid == 0) {
            unsigned dn = atomicAdd(&g_done, 1u);
            if (dn == LOGZ_BLOCKS - 1) {
                g_done = 0;
                g_bar_gen = 0;
                __threadfence();
            }
        }
        return;
    }

    // ======= psi path: 128 blocks x 64 samples, mma.sync tf32 (3xTF32) =======
    const int bi = blockIdx.x - LOGZ_BLOCKS;
    const int m0 = bi * MBLK;
    const int lane = tid & 31;
    const int w = tid >> 5;
    const int g = lane >> 2, tq = lane & 3;
    const int mtile = w & 3;          // rows 16*mtile .. +15
    const int h = w >> 2;             // n half: 0 = phys branch 0, 1 = branch 1
    const int r0 = mtile * 16 + g, r1 = r0 + 8;
    unsigned char* cfgS = (unsigned char*)(smem + SM_CFG);
    const unsigned smemB_base = (unsigned)__cvta_generic_to_shared(smem + SM_B);

    // prefetch B(site0) into buffer 0: 4096 float4 / 256 thr
    {
        const float4* src = (const float4*)g_bulkT;
#pragma unroll
        for (int i = 0; i < 16; i++)
            cp16(smemB_base + (unsigned)(tid + (i << 8)) * 16u, src + tid + (i << 8));
        cp_commit();
    }

    // stage cfg + right
    for (int idx = tid; idx < 64 * MBLK; idx += NTHREADS) {
        int mm = idx >> 6, s = idx & 63;
        cfgS[s * MBLK + mm] = (unsigned char)cfg[(size_t)(m0 + mm) * 64 + s];
    }
    if (tid < 128) smem[SM_RIGHT + tid] = right[tid];
    __syncthreads();

    // env0[m][k] = left[cfg0(m)][k]
    for (int idx = tid; idx < 64 * 64; idx += NTHREADS) {
        int k = idx >> 6, mm = idx & 63;
        smem[SM_ENV + mm * ENV_STRIDE + k] = left[(int)cfgS[mm] * 64 + k];
    }

    float ps0 = 0.0f, ps1 = 0.0f;

    for (int t = 0; t < NBULK; t++) {
        cp_wait0();
        __syncthreads();   // B[t] resident; env stores from t-1 visible

        // ---- load A fragments (env rows r0, r1), split hi/lo tf32 ----
        unsigned ah[8][4], al[8][4];
#pragma unroll
        for (int kt = 0; kt < 8; kt++) {
            const int c0 = kt * 8 + tq;
            float v0 = smem[SM_ENV + r0 * ENV_STRIDE + c0];
            float v1 = smem[SM_ENV + r1 * ENV_STRIDE + c0];
            float v2 = smem[SM_ENV + r0 * ENV_STRIDE + c0 + 4];
            float v3 = smem[SM_ENV + r1 * ENV_STRIDE + c0 + 4];
            unsigned h0 = __float_as_uint(v0) & 0xFFFFE000u;
            unsigned h1 = __float_as_uint(v1) & 0xFFFFE000u;
            unsigned h2 = __float_as_uint(v2) & 0xFFFFE000u;
            unsigned h3 = __float_as_uint(v3) & 0xFFFFE000u;
            ah[kt][0] = h0; ah[kt][1] = h1; ah[kt][2] = h2; ah[kt][3] = h3;
            al[kt][0] = __float_as_uint(v0 - __uint_as_float(h0)) & 0xFFFFE000u;
            al[kt][1] = __float_as_uint(v1 - __uint_as_float(h1)) & 0xFFFFE000u;
            al[kt][2] = __float_as_uint(v2 - __uint_as_float(h2)) & 0xFFFFE000u;
            al[kt][3] = __float_as_uint(v3 - __uint_as_float(h3)) & 0xFFFFE000u;
        }

        // prefetch B(t+1)
        if (t + 1 < NBULK) {
            const float4* src = (const float4*)(g_bulkT + (size_t)(t + 1) * 16384);
            unsigned dst = smemB_base + (unsigned)(((t + 1) & 1) * 65536u);
#pragma unroll
            for (int i = 0; i < 16; i++)
                cp16(dst + (unsigned)(tid + (i << 8)) * 16u, src + tid + (i << 8));
            cp_commit();
        }
        __syncthreads();   // all A reads done -> epilogue stores below are safe

        // ---- MMA: D[64m x 128n] = env @ [A0|A1], 3xTF32 ----
        const float4* Bh4 = (const float4*)(smem + SM_B + (t & 1) * 16384);
        const float4* Bl4 = Bh4 + 2048;     // +8192 floats
        const int pbase = (h << 2);         // ntp global base for this warp

        float d[8][4];
#pragma unroll
        for (int i = 0; i < 8; i++) { d[i][0] = 0.f; d[i][1] = 0.f; d[i][2] = 0.f; d[i][3] = 0.f; }

#pragma unroll
        for (int kt = 0; kt < 8; kt++) {
            float4 bh[4];
#pragma unroll
            for (int p = 0; p < 4; p++)
                bh[p] = Bh4[kt * 256 + (pbase + p) * 32 + lane];
#pragma unroll
            for (int ntl = 0; ntl < 8; ntl++) {
                unsigned b0 = __float_as_uint((ntl & 1) ? bh[ntl >> 1].z : bh[ntl >> 1].x);
                unsigned b1 = __float_as_uint((ntl & 1) ? bh[ntl >> 1].w : bh[ntl >> 1].y);
                mma8(d[ntl][0], d[ntl][1], d[ntl][2], d[ntl][3],
                     ah[kt][0], ah[kt][1], ah[kt][2], ah[kt][3], b0, b1);
                mma8(d[ntl][0], d[ntl][1], d[ntl][2], d[ntl][3],
                     al[kt][0], al[kt][1], al[kt][2], al[kt][3], b0, b1);
            }
            float4 bl[4];
#pragma unroll
            for (int p = 0; p < 4; p++)
                bl[p] = Bl4[kt * 256 + (pbase + p) * 32 + lane];
#pragma unroll
            for (int ntl = 0; ntl < 8; ntl++) {
                unsigned b0 = __float_as_uint((ntl & 1) ? bl[ntl >> 1].z : bl[ntl >> 1].x);
                unsigned b1 = __float_as_uint((ntl & 1) ? bl[ntl >> 1].w : bl[ntl >> 1].y);
                mma8(d[ntl][0], d[ntl][1], d[ntl][2], d[ntl][3],
                     ah[kt][0], ah[kt][1], ah[kt][2], ah[kt][3], b0, b1);
            }
        }

        // ---- epilogue ----
        if (t < NBULK - 1) {
            const int sel0 = cfgS[(t + 1) * MBLK + r0];
            const int sel1 = cfgS[(t + 1) * MBLK + r1];
#pragma unroll
            for (int ntl = 0; ntl < 8; ntl++) {
                const int j0 = ntl * 8 + 2 * tq;
                if (sel0 == h)
                    *(float2*)&smem[SM_ENV + r0 * ENV_STRIDE + j0] = make_float2(d[ntl][0], d[ntl][1]);
                if (sel1 == h)
                    *(float2*)&smem[SM_ENV + r1 * ENV_STRIDE + j0] = make_float2(d[ntl][2], d[ntl][3]);
            }
        } else {
            // final: select env_62 (cfg col 62), dot with right[:, cfg col 63]
            const int sel0 = cfgS[62 * MBLK + r0], sl0 = cfgS[63 * MBLK + r0];
            const int sel1 = cfgS[62 * MBLK + r1], sl1 = cfgS[63 * MBLK + r1];
#pragma unroll
            for (int ntl = 0; ntl < 8; ntl++) {
                const int j0 = ntl * 8 + 2 * tq;
                if (sel0 == h) {
                    ps0 = fmaf(d[ntl][0], smem[SM_RIGHT + j0 * 2 + sl0], ps0);
                    ps0 = fmaf(d[ntl][1], smem[SM_RIGHT + (j0 + 1) * 2 + sl0], ps0);
                }
                if (sel1 == h) {
                    ps1 = fmaf(d[ntl][2], smem[SM_RIGHT + j0 * 2 + sl1], ps1);
                    ps1 = fmaf(d[ntl][3], smem[SM_RIGHT + (j0 + 1) * 2 + sl1], ps1);
                }
            }
        }
    }

    // reduce psi partials: lanes sharing a row differ in tq (xor 1, 2)
    ps0 += __shfl_xor_sync(0xffffffffu, ps0, 1);
    ps0 += __shfl_xor_sync(0xffffffffu, ps0, 2);
    ps1 += __shfl_xor_sync(0xffffffffu, ps1, 1);
    ps1 += __shfl_xor_sync(0xffffffffu, ps1, 2);
    __syncthreads();           // env no longer needed; reuse RED area safely
    if (tq == 0) {
        smem[SM_RED + h * 64 + r0] = ps0;
        smem[SM_RED + h * 64 + r1] = ps1;
    }
    __syncthreads();
    if (tid < 64) {
        float psi = smem[SM_RED + tid] + smem[SM_RED + 64 + tid];
        smem[SM_RED + tid] = logf(fmaxf(psi * psi, 1e-12f));
    }
    __syncthreads();
    if (tid == 0) {
        float s = 0.0f;
#pragma unroll 8
        for (int i = 0; i < 64; i++) s += smem[SM_RED + i];
        g_blocksums[bi] = s;
        __threadfence();
        unsigned o = atomicAdd(&g_fin, 1u);
        if (o == PSI_BLOCKS) {   // last arrival overall (128 psi + 1 logz)
            float tot = 0.0f;
            for (int i = 0; i < PSI_BLOCKS; i++) tot += __ldcg(&g_blocksums[i]);
            out[0] = g_logz - tot * (1.0f / (float)NBATCH);
            __threadfence();
            g_fin = 0;
            __threadfence();
        }
    }
}

extern "C" void kernel_launch(void* const* d_in, const int* in_sizes, int n_in,
                              void* d_out, int out_size) {
    const int*   cfg   = (const int*)d_in[0];
    const float* left  = (const float*)d_in[1];
    const float* bulk  = (const float*)d_in[2];
    const float* right = (const float*)d_in[3];

    cudaFuncSetAttribute(main_kernel, cudaFuncAttributeMaxDynamicSharedMemorySize,
                         SM_TOTALF * 4);

    pre_kernel<<<NBULK, NTHREADS>>>(bulk);
    main_kernel<<<TOTAL_BLOCKS, NTHREADS, SM_TOTALF * 4>>>(cfg, left, bulk, right,
                                                           (float*)d_out);
}